// round 1
// baseline (speedup 1.0000x reference)
#include <cuda_runtime.h>

#define BATCH 2
#define NN 1024
#define CC 64
#define ROWS (BATCH * NN)   // 2048
#define TP 68               // padded smem stride (floats)

// Scratch (no allocs allowed): Y = X @ W, R = rownorm2(Y)
__device__ float g_Y[ROWS * CC];
__device__ float g_R[ROWS];

// ---------------------------------------------------------------------------
// Kernel A: Y[row, d] = sum_c X[row, c] * W[c, d];  R[row] = ||Y[row]||^2
// 256 threads = 8 warps = 8 rows per block; each lane computes 2 output cols.
// ---------------------------------------------------------------------------
__global__ void y_kernel(const float* __restrict__ X, const float* __restrict__ W) {
    __shared__ float Ws[64 * 64];   // [c][d], d contiguous -> conflict-free
    __shared__ float Xs[8 * 64];
    const int tid = threadIdx.x;

    #pragma unroll
    for (int i = tid; i < 64 * 64; i += 256) Ws[i] = W[i];
    const int rowBase = blockIdx.x * 8;
    for (int i = tid; i < 8 * 64; i += 256) Xs[i] = X[rowBase * 64 + i];
    __syncthreads();

    const int warp = tid >> 5, lane = tid & 31;
    float a0 = 0.f, a1 = 0.f;
    #pragma unroll
    for (int c0 = 0; c0 < 64; c0++) {
        const float xv = Xs[warp * 64 + c0];          // broadcast
        a0 = fmaf(xv, Ws[c0 * 64 + lane],      a0);   // conflict-free
        a1 = fmaf(xv, Ws[c0 * 64 + lane + 32], a1);
    }
    const int row = rowBase + warp;
    g_Y[row * 64 + lane]      = a0;
    g_Y[row * 64 + lane + 32] = a1;

    float s = a0 * a0 + a1 * a1;
    #pragma unroll
    for (int o = 16; o; o >>= 1) s += __shfl_xor_sync(0xffffffffu, s, o);
    if (lane == 0) g_R[row] = s;
}

// ---------------------------------------------------------------------------
// Kernel B: 64x64 output tile per block; symmetric (ti >= tj), mirror-write.
// q_ij = R_i + R_j - 2 * <y_i, y_j>;  adj = exp(-q) (+1 on global diagonal).
// smem d-major [d][row] with stride 68: outer-product loop, float4 fragment
// loads (A: 2-way broadcast across warp, B: 2-way conflict), 16 FFMA per d.
// ---------------------------------------------------------------------------
__global__ void adj_kernel(float* __restrict__ out) {
    const int tj = blockIdx.x, ti = blockIdx.y, b = blockIdx.z;
    if (ti < tj) return;   // symmetry: only lower-triangular tiles do work

    __shared__ float Yi[64 * TP];
    __shared__ float Yj[64 * TP];
    __shared__ float Ri[64], Rj[64];

    const int tid = threadIdx.x;
    const int gi = b * NN + ti * 64;
    const int gj = b * NN + tj * 64;

    // Transposed load: smem[d * TP + r] = Y[(g + r) * 64 + d]
    for (int idx = tid; idx < 4096; idx += 256) {
        const int r = idx >> 6, d = idx & 63;
        Yi[d * TP + r] = g_Y[(gi + r) * 64 + d];
        Yj[d * TP + r] = g_Y[(gj + r) * 64 + d];
    }
    if (tid < 64)        Ri[tid]      = g_R[gi + tid];
    else if (tid < 128)  Rj[tid - 64] = g_R[gj + tid - 64];
    __syncthreads();

    const int tx = tid & 15;   // column group (j)
    const int ty = tid >> 4;   // row group (i)

    float acc[4][4];
    #pragma unroll
    for (int l = 0; l < 4; l++)
        #pragma unroll
        for (int k = 0; k < 4; k++) acc[l][k] = 0.f;

    #pragma unroll 4
    for (int d = 0; d < 64; d++) {
        const float4 av = *(const float4*)&Yi[d * TP + ty * 4];
        const float4 bv = *(const float4*)&Yj[d * TP + tx * 4];
        const float a[4]  = {av.x, av.y, av.z, av.w};
        const float bb[4] = {bv.x, bv.y, bv.z, bv.w};
        #pragma unroll
        for (int l = 0; l < 4; l++)
            #pragma unroll
            for (int k = 0; k < 4; k++)
                acc[l][k] = fmaf(a[l], bb[k], acc[l][k]);
    }

    // Epilogue: q -> exp(-q), +1 on global diagonal
    const size_t outBase = (size_t)b * (size_t)NN * (size_t)NN;
    float v[4][4];
    #pragma unroll
    for (int l = 0; l < 4; l++) {
        const int i = ty * 4 + l;
        const float ri = Ri[i];
        #pragma unroll
        for (int k = 0; k < 4; k++) {
            const int j = tx * 4 + k;
            const float q = ri + Rj[j] - 2.f * acc[l][k];
            float e = __expf(-q);
            if (ti == tj && i == j) e += 1.f;
            v[l][k] = e;
        }
    }

    // Primary write: float4 per row-sub (coalesced: tx contiguous columns)
    #pragma unroll
    for (int l = 0; l < 4; l++) {
        const int grow = ti * 64 + ty * 4 + l;
        const float4 w4 = make_float4(v[l][0], v[l][1], v[l][2], v[l][3]);
        *(float4*)&out[outBase + (size_t)grow * NN + tj * 64 + tx * 4] = w4;
    }

    // Mirror write via smem transpose (coalesced), skip diagonal tiles
    if (ti != tj) {
        __syncthreads();                 // done reading Yi in compute loop
        #pragma unroll
        for (int l = 0; l < 4; l++)
            #pragma unroll
            for (int k = 0; k < 4; k++)
                Yi[(tx * 4 + k) * TP + (ty * 4 + l)] = v[l][k];
        __syncthreads();
        for (int idx = tid; idx < 4096; idx += 256) {
            const int r = idx >> 6, c2 = idx & 63;
            out[outBase + (size_t)(tj * 64 + r) * NN + ti * 64 + c2] = Yi[r * TP + c2];
        }
    }
}

// ---------------------------------------------------------------------------
extern "C" void kernel_launch(void* const* d_in, const int* in_sizes, int n_in,
                              void* d_out, int out_size) {
    const float* X = (const float*)d_in[0];   // regional_means (2,1024,64)
    const float* W = (const float*)d_in[1];   // W (64,64)
    // d_in[2] = c (=64), unused
    float* out = (float*)d_out;               // (2,1024,1024) fp32

    y_kernel<<<ROWS / 8, 256>>>(X, W);
    adj_kernel<<<dim3(16, 16, 2), 256>>>(out);
    (void)in_sizes; (void)n_in; (void)out_size;
}

// round 2
// speedup vs baseline: 1.2137x; 1.2137x over previous
#include <cuda_runtime.h>

#define BATCH 2
#define NN 1024
#define CC 64
#define ROWS (BATCH * NN)   // 2048

// Scratch: Yt = (X @ W)^T laid out [d][row], R = rownorm2
__device__ float g_Yt[CC * ROWS];
__device__ float g_R[ROWS];

// ---------------------------------------------------------------------------
// Kernel A: Y[row,d] = sum_c X[row,c] W[c,d]; store transposed g_Yt[d*ROWS+row]
// and R[row] = ||Y[row]||^2. 256 threads = 8 rows/block.
// ---------------------------------------------------------------------------
__global__ void y_kernel(const float* __restrict__ X, const float* __restrict__ W) {
    __shared__ float Ws[64 * 64];
    __shared__ float Xs[8 * 64];
    const int tid = threadIdx.x;

    for (int i = tid; i < 64 * 64; i += 256) Ws[i] = W[i];
    const int rowBase = blockIdx.x * 8;
    for (int i = tid; i < 8 * 64; i += 256) Xs[i] = X[rowBase * 64 + i];
    __syncthreads();

    const int warp = tid >> 5, lane = tid & 31;
    float a0 = 0.f, a1 = 0.f;
    #pragma unroll
    for (int c0 = 0; c0 < 64; c0++) {
        const float xv = Xs[warp * 64 + c0];
        a0 = fmaf(xv, Ws[c0 * 64 + lane],      a0);
        a1 = fmaf(xv, Ws[c0 * 64 + lane + 32], a1);
    }
    const int row = rowBase + warp;
    g_Yt[lane * ROWS + row]        = a0;   // scattered, small total traffic
    g_Yt[(lane + 32) * ROWS + row] = a1;

    float s = a0 * a0 + a1 * a1;
    #pragma unroll
    for (int o = 16; o; o >>= 1) s += __shfl_xor_sync(0xffffffffu, s, o);
    if (lane == 0) g_R[row] = s;
}

// ---------------------------------------------------------------------------
// Kernel B: symmetric Gram + exp. 64x64 tile per block, 128 threads,
// 8x4 register tile per thread. Triangular grid: blockIdx.x in [0,136).
// q_ij = R_i + R_j - 2<y_i,y_j>; adj = exp(-q) (+1 on global diag).
// ---------------------------------------------------------------------------
__global__ void adj_kernel(float* __restrict__ out) {
    const int t = blockIdx.x, b = blockIdx.y;
    // triangular index -> (ti, tj), ti >= tj
    int ti = (int)((sqrtf(8.0f * (float)t + 1.0f) - 1.0f) * 0.5f);
    while ((ti + 1) * (ti + 2) / 2 <= t) ti++;
    while (ti * (ti + 1) / 2 > t) ti--;
    const int tj = t - ti * (ti + 1) / 2;

    __shared__ float Yi[64 * 64];
    __shared__ float Yj[64 * 64];
    __shared__ float Ri[64], Rj[64];

    const int tid = threadIdx.x;
    const int gi = b * NN + ti * 64;
    const int gj = b * NN + tj * 64;

    // Coalesced load from d-major g_Yt; conflict-free smem store.
    #pragma unroll
    for (int idx = tid; idx < 4096; idx += 128) {
        const int d = idx >> 6, r = idx & 63;
        Yi[idx] = g_Yt[d * ROWS + gi + r];
        Yj[idx] = g_Yt[d * ROWS + gj + r];
    }
    if (tid < 64)       Ri[tid]      = g_R[gi + tid];
    else                Rj[tid - 64] = g_R[gj + (tid - 64)];
    __syncthreads();

    const int tx = tid & 15;   // j group: 4 cols
    const int ty = tid >> 4;   // i group: 8 rows

    float acc[8][4];
    #pragma unroll
    for (int l = 0; l < 8; l++)
        #pragma unroll
        for (int k = 0; k < 4; k++) acc[l][k] = 0.f;

    #pragma unroll 8
    for (int d = 0; d < 64; d++) {
        const float4 a0 = *(const float4*)&Yi[d * 64 + ty * 8];
        const float4 a1 = *(const float4*)&Yi[d * 64 + ty * 8 + 4];
        const float4 bv = *(const float4*)&Yj[d * 64 + tx * 4];
        const float av[8] = {a0.x, a0.y, a0.z, a0.w, a1.x, a1.y, a1.z, a1.w};
        const float bb[4] = {bv.x, bv.y, bv.z, bv.w};
        #pragma unroll
        for (int l = 0; l < 8; l++)
            #pragma unroll
            for (int k = 0; k < 4; k++)
                acc[l][k] = fmaf(av[l], bb[k], acc[l][k]);
    }

    // Epilogue
    const size_t outBase = (size_t)b * (size_t)NN * (size_t)NN;
    float v[8][4];
    #pragma unroll
    for (int l = 0; l < 8; l++) {
        const int i = ty * 8 + l;
        const float ri = Ri[i];
        #pragma unroll
        for (int k = 0; k < 4; k++) {
            const int j = tx * 4 + k;
            const float q = ri + Rj[j] - 2.f * acc[l][k];
            float e = __expf(-q);
            if (ti == tj && i == j) e += 1.f;
            v[l][k] = e;
        }
    }

    // Primary write: one float4 per row (coalesced across tx).
    #pragma unroll
    for (int l = 0; l < 8; l++) {
        const int grow = ti * 64 + ty * 8 + l;
        *(float4*)&out[outBase + (size_t)grow * NN + tj * 64 + tx * 4] =
            make_float4(v[l][0], v[l][1], v[l][2], v[l][3]);
    }

    // Mirror write directly from registers: per thread, per transposed row k,
    // 8 consecutive floats (ty*8 .. +8) -> two float4 stores. No syncs needed.
    if (ti != tj) {
        #pragma unroll
        for (int k = 0; k < 4; k++) {
            const int grow = tj * 64 + tx * 4 + k;
            const size_t base = outBase + (size_t)grow * NN + ti * 64 + ty * 8;
            *(float4*)&out[base]     = make_float4(v[0][k], v[1][k], v[2][k], v[3][k]);
            *(float4*)&out[base + 4] = make_float4(v[4][k], v[5][k], v[6][k], v[7][k]);
        }
    }
}

// ---------------------------------------------------------------------------
extern "C" void kernel_launch(void* const* d_in, const int* in_sizes, int n_in,
                              void* d_out, int out_size) {
    const float* X = (const float*)d_in[0];   // (2,1024,64)
    const float* W = (const float*)d_in[1];   // (64,64)
    float* out = (float*)d_out;               // (2,1024,1024)

    y_kernel<<<ROWS / 8, 256>>>(X, W);
    adj_kernel<<<dim3(136, 2), 128>>>(out);
    (void)in_sizes; (void)n_in; (void)out_size;
}

// round 3
// speedup vs baseline: 1.2322x; 1.0153x over previous
#include <cuda_runtime.h>

#define BATCH 2
#define NN 1024
#define CC 64
#define ROWS (BATCH * NN)   // 2048

// Scale folded into Y: yhat = sqrt(2*log2e) * y, so <yhat_i,yhat_j> = 2*log2e*<y_i,y_j>
// R holds log2e*||y||^2 = 0.5*||yhat||^2.  Then t = acc - R_i - R_j = -log2e * q.
#define SCALE_Y 1.6983709f   // sqrt(2 * 1.44269504)

__device__ float g_Yt[CC * ROWS];   // [d][row], row-contiguous
__device__ float g_R[ROWS];

// ---------------------------------------------------------------------------
// Kernel A: Y = X @ W (scaled), transposed store + row norms.
// grid 128 x 256 threads; 16 rows per block (2 rows per warp).
// ---------------------------------------------------------------------------
__global__ void y_kernel(const float* __restrict__ X, const float* __restrict__ W) {
    __shared__ float Ws[64 * 64];   // [c][d]
    __shared__ float Xs[16 * 64];
    __shared__ float Ys[64 * 17];   // transposed staging, stride 17 (odd) = conflict-free
    const int tid = threadIdx.x;
    const int rowBase = blockIdx.x * 16;

    for (int i = tid; i < 64 * 64; i += 256) Ws[i] = W[i];
    for (int i = tid; i < 16 * 64; i += 256) Xs[i] = X[rowBase * 64 + i];
    __syncthreads();

    const int warp = tid >> 5, lane = tid & 31;
    #pragma unroll
    for (int r8 = 0; r8 < 2; r8++) {
        const int row = warp * 2 + r8;
        float a0 = 0.f, a1 = 0.f;
        #pragma unroll
        for (int c0 = 0; c0 < 64; c0++) {
            const float xv = Xs[row * 64 + c0];
            a0 = fmaf(xv, Ws[c0 * 64 + lane],      a0);
            a1 = fmaf(xv, Ws[c0 * 64 + lane + 32], a1);
        }
        a0 *= SCALE_Y; a1 *= SCALE_Y;
        Ys[lane * 17 + row]        = a0;   // conflict-free (stride 17)
        Ys[(lane + 32) * 17 + row] = a1;
        float s = a0 * a0 + a1 * a1;
        #pragma unroll
        for (int o = 16; o; o >>= 1) s += __shfl_xor_sync(0xffffffffu, s, o);
        if (lane == 0) g_R[rowBase + row] = 0.5f * s;
    }
    __syncthreads();
    // coalesced transposed store: g_Yt[d][rowBase + r]
    for (int idx = tid; idx < 64 * 16; idx += 256) {
        const int d = idx >> 4, r = idx & 15;
        g_Yt[d * ROWS + rowBase + r] = Ys[d * 17 + r];
    }
}

// ---------------------------------------------------------------------------
// Kernel B: symmetric Gram + MUFU-free exp. 136 blocks (triangular 16x16
// tiles), 256 threads: warps 0-3 handle batch 0, warps 4-7 batch 1.
// Per 128-thread half: 64x64 tile, 8x4 register tile per thread.
// ---------------------------------------------------------------------------
__global__ void adj_kernel(float* __restrict__ out) {
    extern __shared__ float sm[];
    const int tid = threadIdx.x;
    const int b = tid >> 7;            // batch (half-block)
    const int tid2 = tid & 127;

    const int t = blockIdx.x;
    int ti = (int)((sqrtf(8.0f * (float)t + 1.0f) - 1.0f) * 0.5f);
    while ((ti + 1) * (ti + 2) / 2 <= t) ti++;
    while (ti * (ti + 1) / 2 > t) ti--;
    const int tj = t - ti * (ti + 1) / 2;

    float* Yi = sm + b * 8320;         // 4096 + 4096 + 64 + 64 per half
    float* Yj = Yi + 4096;
    float* Ri = Yj + 4096;
    float* Rj = Ri + 64;

    const int gi = b * NN + ti * 64;
    const int gj = b * NN + tj * 64;

    for (int idx = tid2; idx < 4096; idx += 128) {
        const int d = idx >> 6, r = idx & 63;
        Yi[idx] = g_Yt[d * ROWS + gi + r];
        Yj[idx] = g_Yt[d * ROWS + gj + r];
    }
    if (tid2 < 64)  Ri[tid2]      = g_R[gi + tid2];
    else            Rj[tid2 - 64] = g_R[gj + (tid2 - 64)];
    __syncthreads();

    const int tx = tid2 & 15;   // 4 cols
    const int ty = tid2 >> 4;   // 8 rows

    float acc[8][4];
    #pragma unroll
    for (int l = 0; l < 8; l++)
        #pragma unroll
        for (int k = 0; k < 4; k++) acc[l][k] = 0.f;

    #pragma unroll 8
    for (int d = 0; d < 64; d++) {
        const float4 a0 = *(const float4*)&Yi[d * 64 + ty * 8];
        const float4 a1 = *(const float4*)&Yi[d * 64 + ty * 8 + 4];
        const float4 bv = *(const float4*)&Yj[d * 64 + tx * 4];
        const float av[8] = {a0.x, a0.y, a0.z, a0.w, a1.x, a1.y, a1.z, a1.w};
        const float bb[4] = {bv.x, bv.y, bv.z, bv.w};
        #pragma unroll
        for (int l = 0; l < 8; l++)
            #pragma unroll
            for (int k = 0; k < 4; k++)
                acc[l][k] = fmaf(av[l], bb[k], acc[l][k]);
    }

    float Rli[8], Rlj[4];
    #pragma unroll
    for (int l = 0; l < 8; l++) Rli[l] = Ri[ty * 8 + l];
    #pragma unroll
    for (int k = 0; k < 4; k++) Rlj[k] = Rj[tx * 4 + k];

    // ---- MUFU-free exp: result = 2^t, t = acc - Rli - Rlj  (t = -log2e*q) ----
    const float MAGIC = 12582912.0f;                 // 2^23 + 2^22
    const int   MAGIC_I = 0x4B400000;
    #pragma unroll
    for (int l = 0; l < 8; l++) {
        #pragma unroll
        for (int k = 0; k < 4; k++) {
            float tt = (acc[l][k] - Rli[l]) - Rlj[k];
            float sh = tt + MAGIC;                   // round-to-nearest encode
            float rn = sh - MAGIC;
            float f  = tt - rn;                      // f in [-0.5, 0.5]
            int   n  = __float_as_int(sh) - MAGIC_I; // rn as integer
            // 2^f, degree-6 Taylor (rel err ~1e-7 on [-0.5,0.5])
            float p = 1.5403530e-4f;
            p = fmaf(p, f, 1.3333558e-3f);
            p = fmaf(p, f, 9.6181291e-3f);
            p = fmaf(p, f, 5.5504109e-2f);
            p = fmaf(p, f, 2.4022651e-1f);
            p = fmaf(p, f, 6.9314718e-1f);
            p = fmaf(p, f, 1.0f);
            float sc = __int_as_float((n + 127) << 23);
            float e  = (n < -126) ? 0.0f : p * sc;   // FTZ like __expf
            if (ti == tj && (ty * 8 + l) == (tx * 4 + k)) e += 1.0f;
            acc[l][k] = e;
        }
    }

    const size_t outBase = (size_t)b * (size_t)NN * (size_t)NN;

    // Primary write (coalesced float4 across tx)
    #pragma unroll
    for (int l = 0; l < 8; l++) {
        const int grow = ti * 64 + ty * 8 + l;
        *(float4*)&out[outBase + (size_t)grow * NN + tj * 64 + tx * 4] =
            make_float4(acc[l][0], acc[l][1], acc[l][2], acc[l][3]);
    }

    // Mirror write from registers (two float4 per transposed row)
    if (ti != tj) {
        #pragma unroll
        for (int k = 0; k < 4; k++) {
            const int grow = tj * 64 + tx * 4 + k;
            const size_t base = outBase + (size_t)grow * NN + ti * 64 + ty * 8;
            *(float4*)&out[base]     = make_float4(acc[0][k], acc[1][k], acc[2][k], acc[3][k]);
            *(float4*)&out[base + 4] = make_float4(acc[4][k], acc[5][k], acc[6][k], acc[7][k]);
        }
    }
}

// ---------------------------------------------------------------------------
extern "C" void kernel_launch(void* const* d_in, const int* in_sizes, int n_in,
                              void* d_out, int out_size) {
    const float* X = (const float*)d_in[0];   // (2,1024,64)
    const float* W = (const float*)d_in[1];   // (64,64)
    float* out = (float*)d_out;               // (2,1024,1024)

    static int smem_set = 0;
    const int smemBytes = 2 * 8320 * (int)sizeof(float);   // 66560
    if (!smem_set) {
        cudaFuncSetAttribute(adj_kernel, cudaFuncAttributeMaxDynamicSharedMemorySize, smemBytes);
        smem_set = 1;
    }

    y_kernel<<<128, 256>>>(X, W);
    adj_kernel<<<136, 256, smemBytes>>>(out);
    (void)in_sizes; (void)n_in; (void)out_size;
}